// round 7
// baseline (speedup 1.0000x reference)
#include <cuda_runtime.h>
#include <cstdint>

#define NN   10000
#define EE   320000
#define FIN  512
#define NHID 32
#define LAT  16
#define PAD  128
#define TT   79      // ceil(10000/128) tiles per dim
#define NTRI 3160    // TT*(TT+1)/2

typedef unsigned long long u64;

// ---------------- device scratch (no allocations allowed) ----------------
// g_cnt invariant: zero at module load; k_spmm2 restores it to zero after
// its reads, so every kernel_launch call (and graph replay) sees zeros.
__device__ int   g_cnt[NN];
__device__ int   g_src[NN * PAD];
__device__ float g_wgt[NN * PAD];
__device__ float g_h0 [NN * NHID];
__device__ float g_z0 [NN * LAT];

// ---------------- f32x2 packed helpers (sm_103a FFMA2 path) --------------
__device__ __forceinline__ u64 fma2(u64 a, u64 b, u64 c) {
    u64 d;
    asm("fma.rn.f32x2 %0, %1, %2, %3;" : "=l"(d) : "l"(a), "l"(b), "l"(c));
    return d;
}
__device__ __forceinline__ u64 pack2(float x) {
    u64 d; asm("mov.b64 %0, {%1, %1};" : "=l"(d) : "f"(x)); return d;
}
__device__ __forceinline__ float lo2(u64 v) {
    float f; asm("{ .reg .f32 h; mov.b64 {%0, h}, %1; }" : "=f"(f) : "l"(v)); return f;
}
__device__ __forceinline__ float hi2(u64 v) {
    float f; asm("{ .reg .f32 l; mov.b64 {l, %0}, %1; }" : "=f"(f) : "l"(v)); return f;
}
__device__ __forceinline__ float sigmoid_fast(float x) {
    float t;
    asm("tanh.approx.f32 %0, %1;" : "=f"(t) : "f"(0.5f * x));
    return fmaf(0.5f, t, 0.5f);
}
__device__ __forceinline__ u64 sig2(u64 x) {
    float lo = sigmoid_fast(lo2(x));
    float hi = sigmoid_fast(hi2(x));
    u64 r; asm("mov.b64 %0, {%1, %2};" : "=l"(r) : "f"(lo), "f"(hi));
    return r;
}

// ---------------- adjacency build ----------------------------------------
__global__ void __launch_bounds__(256) k_build(const int* __restrict__ ei,
                                               const float* __restrict__ ew) {
    int e = blockIdx.x * blockDim.x + threadIdx.x;
    if (e >= EE) return;
    int   s = ei[e];
    int   d = ei[EE + e];
    float w = ew[e];
    int p = atomicAdd(&g_cnt[d], 1);
    if (p < PAD) {
        g_src[d * PAD + p] = s;
        g_wgt[d * PAD + p] = w;
    }
}

// ---------------- GEMM1: h0[N,32] = x[N,512] @ W1[512,32], FFMA2 ---------
__global__ void __launch_bounds__(256) k_gemm1(const float* __restrict__ x,
                                               const float* __restrict__ W1) {
    __shared__ float xs[64][28];
    __shared__ float w1s[16][32];

    int t    = threadIdx.x;
    int row0 = blockIdx.x * 64;
    int cg   = (t & 7) << 2;
    int rs   = (t >> 3) << 1;

    u64 a00 = 0ull, a01 = 0ull, a10 = 0ull, a11 = 0ull;

    for (int kk = 0; kk < FIN; kk += 16) {
        {
            int r  = t >> 2;
            int kq = (t & 3) << 2;
            int gr = row0 + r;
            float4 v = make_float4(0.f, 0.f, 0.f, 0.f);
            if (gr < NN) v = *(const float4*)(x + (size_t)gr * FIN + kk + kq);
            *(float4*)&xs[r][kq] = v;
        }
        if (t < 128) {
            int k = t >> 3, c = (t & 7) << 2;
            *(float4*)&w1s[k][c] = *(const float4*)(W1 + (size_t)(kk + k) * NHID + c);
        }
        __syncthreads();

        #pragma unroll
        for (int k = 0; k < 16; k++) {
            ulonglong2 bb = *(const ulonglong2*)&w1s[k][cg];
            u64 a0 = pack2(xs[rs][k]);
            u64 a1 = pack2(xs[rs + 1][k]);
            a00 = fma2(a0, bb.x, a00); a01 = fma2(a0, bb.y, a01);
            a10 = fma2(a1, bb.x, a10); a11 = fma2(a1, bb.y, a11);
        }
        __syncthreads();
    }

    int gr0 = row0 + rs;
    if (gr0 < NN)
        *(float4*)&g_h0[(size_t)gr0 * NHID + cg] =
            make_float4(lo2(a00), hi2(a00), lo2(a01), hi2(a01));
    if (gr0 + 1 < NN)
        *(float4*)&g_h0[(size_t)(gr0 + 1) * NHID + cg] =
            make_float4(lo2(a10), hi2(a10), lo2(a11), hi2(a11));
}

// ------- Fused SpMM1 + GEMM2: z0[d,:] = (sum_e w_e*h0[src_e,:]) @ W2 -----
__global__ void __launch_bounds__(256) k_spmm1_gemm2(const float* __restrict__ W2) {
    __shared__ float w2s[NHID * LAT];
    {
        int t = threadIdx.x;
        for (int i = t; i < NHID * LAT; i += 256) w2s[i] = W2[i];
    }
    __syncthreads();

    int gid  = blockIdx.x * blockDim.x + threadIdx.x;
    int d    = gid >> 5;
    int lane = gid & 31;
    if (d >= NN) return;
    int cnt = g_cnt[d];
    if (cnt > PAD) cnt = PAD;
    const int*   sp = &g_src[d * PAD];
    const float* wp = &g_wgt[d * PAD];
    float acc = 0.f;
    int j = 0;
    for (; j + 8 <= cnt; j += 8) {
        int4   s0 = *(const int4*)  (sp + j);
        int4   s1 = *(const int4*)  (sp + j + 4);
        float4 w0 = *(const float4*)(wp + j);
        float4 w1 = *(const float4*)(wp + j + 4);
        float v0 = g_h0[((size_t)s0.x << 5) + lane];
        float v1 = g_h0[((size_t)s0.y << 5) + lane];
        float v2 = g_h0[((size_t)s0.z << 5) + lane];
        float v3 = g_h0[((size_t)s0.w << 5) + lane];
        float v4 = g_h0[((size_t)s1.x << 5) + lane];
        float v5 = g_h0[((size_t)s1.y << 5) + lane];
        float v6 = g_h0[((size_t)s1.z << 5) + lane];
        float v7 = g_h0[((size_t)s1.w << 5) + lane];
        acc = fmaf(w0.x, v0, acc); acc = fmaf(w0.y, v1, acc);
        acc = fmaf(w0.z, v2, acc); acc = fmaf(w0.w, v3, acc);
        acc = fmaf(w1.x, v4, acc); acc = fmaf(w1.y, v5, acc);
        acc = fmaf(w1.z, v6, acc); acc = fmaf(w1.w, v7, acc);
    }
    for (; j < cnt; j++)
        acc = fmaf(wp[j], g_h0[((size_t)sp[j] << 5) + lane], acc);

    // h[d,:] distributed across lanes; z0[d,c] via shfl broadcast
    int c = lane & 15;
    float zc = 0.f;
    #pragma unroll
    for (int k = 0; k < NHID; k++) {
        float hk = __shfl_sync(0xffffffffu, acc, k);
        zc = fmaf(hk, w2s[k * LAT + c], zc);
    }
    if (lane < LAT)
        g_z0[((size_t)d << 4) + c] = zc;
}

// ------- SpMM2 (+ restore g_cnt=0 for the next call) ---------------------
__global__ void __launch_bounds__(256) k_spmm2(float* __restrict__ zout) {
    int gid = blockIdx.x * blockDim.x + threadIdx.x;
    int d   = gid >> 4;
    int c   = gid & 15;
    int cnt = g_cnt[d];
    if (cnt > PAD) cnt = PAD;
    __syncwarp();                 // all reads of g_cnt in this warp done
    if (c == 0) g_cnt[d] = 0;     // restore invariant for next launch

    const int*   sp = &g_src[d * PAD];
    const float* wp = &g_wgt[d * PAD];
    float acc = 0.f;
    int j = 0;
    for (; j + 8 <= cnt; j += 8) {
        int4   s0 = *(const int4*)  (sp + j);
        int4   s1 = *(const int4*)  (sp + j + 4);
        float4 w0 = *(const float4*)(wp + j);
        float4 w1 = *(const float4*)(wp + j + 4);
        float v0 = g_z0[((size_t)s0.x << 4) + c];
        float v1 = g_z0[((size_t)s0.y << 4) + c];
        float v2 = g_z0[((size_t)s0.z << 4) + c];
        float v3 = g_z0[((size_t)s0.w << 4) + c];
        float v4 = g_z0[((size_t)s1.x << 4) + c];
        float v5 = g_z0[((size_t)s1.y << 4) + c];
        float v6 = g_z0[((size_t)s1.z << 4) + c];
        float v7 = g_z0[((size_t)s1.w << 4) + c];
        acc = fmaf(w0.x, v0, acc); acc = fmaf(w0.y, v1, acc);
        acc = fmaf(w0.z, v2, acc); acc = fmaf(w0.w, v3, acc);
        acc = fmaf(w1.x, v4, acc); acc = fmaf(w1.y, v5, acc);
        acc = fmaf(w1.z, v6, acc); acc = fmaf(w1.w, v7, acc);
    }
    for (; j < cnt; j++)
        acc = fmaf(wp[j], g_z0[((size_t)sp[j] << 4) + c], acc);
    zout[((size_t)d << 4) + c] = acc;
}

// ---------------- Decoder: adj = sigmoid(z @ z^T), symmetric -------------
// 128x128 tile, 512 threads, 4i x 8j per thread (16 u64 accs = 32 regs).
// __launch_bounds__(512,2) caps regs at 64 -> 32 warps/SM (50% occ, 2x
// outstanding stores vs the 8x8 variant). Conflict-free smem layouts kept.
__global__ void __launch_bounds__(512, 2) k_dec(const float* __restrict__ z,
                                                float* __restrict__ out) {
    int b  = blockIdx.x;
    int bi = (int)((159.0f - sqrtf(25281.0f - 8.0f * (float)b)) * 0.5f);
    while (((bi + 1) * TT - ((bi + 1) * bi) / 2) <= b) bi++;
    while ((bi * TT - (bi * (bi - 1)) / 2) > b) bi--;
    int bj = bi + (b - (bi * TT - (bi * (bi - 1)) / 2));

    __shared__ union SmU {
        struct {
            float4 a[16][2][16];   // [k][part][group-of-8]: rows g*8+part*4+e
            float4 b[16][2][16];   // same for j tile
        } in;                      // 16 KB
        float ts[64][128];         // swizzled transpose staging, 32 KB
    } sm;

    int t  = threadIdx.x;
    int i0 = bi * 128;
    int j0 = bj * 128;

    // ---- load both z tiles (512 threads: one row-kq4 pair each) ----
    {
        int r    = t >> 2;            // local row 0..127
        int kq4  = t & 3;
        int part = (r >> 2) & 1;
        int g    = r >> 3;
        int e    = r & 3;

        int gi = i0 + r;
        float4 v = make_float4(0.f, 0.f, 0.f, 0.f);
        if (gi < NN) v = *(const float4*)(z + (size_t)gi * LAT + kq4 * 4);
        ((float*)&sm.in.a[kq4 * 4 + 0][part][g])[e] = v.x;
        ((float*)&sm.in.a[kq4 * 4 + 1][part][g])[e] = v.y;
        ((float*)&sm.in.a[kq4 * 4 + 2][part][g])[e] = v.z;
        ((float*)&sm.in.a[kq4 * 4 + 3][part][g])[e] = v.w;

        int gj = j0 + r;
        float4 u = make_float4(0.f, 0.f, 0.f, 0.f);
        if (gj < NN) u = *(const float4*)(z + (size_t)gj * LAT + kq4 * 4);
        ((float*)&sm.in.b[kq4 * 4 + 0][part][g])[e] = u.x;
        ((float*)&sm.in.b[kq4 * 4 + 1][part][g])[e] = u.y;
        ((float*)&sm.in.b[kq4 * 4 + 2][part][g])[e] = u.z;
        ((float*)&sm.in.b[kq4 * 4 + 3][part][g])[e] = u.w;
    }
    __syncthreads();

    int tx = t & 15, ty = t >> 4;      // tx: j-group (8 cols), ty: i-group (4 rows)
    int ib = ty << 2, jb = tx << 3;

    u64 acc2[4][4];
    #pragma unroll
    for (int r = 0; r < 4; r++)
        #pragma unroll
        for (int q = 0; q < 4; q++) acc2[r][q] = 0ull;

    #pragma unroll
    for (int k = 0; k < 16; k++) {
        float4 Av = sm.in.a[k][ty & 1][ty >> 1];                 // i = ib..ib+3
        ulonglong2 B0 = *(const ulonglong2*)&sm.in.b[k][0][tx];  // (b0,b1)(b2,b3)
        ulonglong2 B1 = *(const ulonglong2*)&sm.in.b[k][1][tx];  // (b4,b5)(b6,b7)
        u64 ar;
        ar = pack2(Av.x);
        acc2[0][0] = fma2(ar, B0.x, acc2[0][0]); acc2[0][1] = fma2(ar, B0.y, acc2[0][1]);
        acc2[0][2] = fma2(ar, B1.x, acc2[0][2]); acc2[0][3] = fma2(ar, B1.y, acc2[0][3]);
        ar = pack2(Av.y);
        acc2[1][0] = fma2(ar, B0.x, acc2[1][0]); acc2[1][1] = fma2(ar, B0.y, acc2[1][1]);
        acc2[1][2] = fma2(ar, B1.x, acc2[1][2]); acc2[1][3] = fma2(ar, B1.y, acc2[1][3]);
        ar = pack2(Av.z);
        acc2[2][0] = fma2(ar, B0.x, acc2[2][0]); acc2[2][1] = fma2(ar, B0.y, acc2[2][1]);
        acc2[2][2] = fma2(ar, B1.x, acc2[2][2]); acc2[2][3] = fma2(ar, B1.y, acc2[2][3]);
        ar = pack2(Av.w);
        acc2[3][0] = fma2(ar, B0.x, acc2[3][0]); acc2[3][1] = fma2(ar, B0.y, acc2[3][1]);
        acc2[3][2] = fma2(ar, B1.x, acc2[3][2]); acc2[3][3] = fma2(ar, B1.y, acc2[3][3]);
    }

    // ---- sigmoid + normal write interleaved per row ----
    int gjw = j0 + jb;
    #pragma unroll
    for (int r = 0; r < 4; r++) {
        acc2[r][0] = sig2(acc2[r][0]);
        acc2[r][1] = sig2(acc2[r][1]);
        acc2[r][2] = sig2(acc2[r][2]);
        acc2[r][3] = sig2(acc2[r][3]);
        int gi = i0 + ib + r;
        if (gi < NN && gjw < NN) {
            float4 o0 = make_float4(lo2(acc2[r][0]), hi2(acc2[r][0]),
                                    lo2(acc2[r][1]), hi2(acc2[r][1]));
            float4 o1 = make_float4(lo2(acc2[r][2]), hi2(acc2[r][2]),
                                    lo2(acc2[r][3]), hi2(acc2[r][3]));
            float* p = out + (size_t)gi * NN + gjw;
            __stcs((float4*)p, o0);
            __stcs((float4*)(p + 4), o1);
        }
    }

    if (bj == bi) return;

    // ---- mirror write: out[j][i], two 64-j-row swizzled transpose passes --
    // Pass p stages j-local rows [64p, 64p+64): threads with tx>>3 == p
    // stage their 8 columns (4-row float4 fragments, XOR-swizzled by
    // key = tx&7 = jl>>3); then each warp reads 4 staged rows conflict-free
    // and streams them out coalesced.
    int warp = t >> 5, lane = t & 31;
    float* tsf = (float*)sm.ts;
    #pragma unroll
    for (int p = 0; p < 2; p++) {
        __syncthreads();    // pass 0: done with in-tiles; pass 1: done with ts
        if ((tx >> 3) == p) {
            int key = tx & 7;
            #pragma unroll
            for (int c = 0; c < 8; c++) {
                int jl = ((tx & 7) << 3) + c;   // staged row 0..63
                int q  = c >> 1;
                float4 v;
                if (c & 1)
                    v = make_float4(hi2(acc2[0][q]), hi2(acc2[1][q]),
                                    hi2(acc2[2][q]), hi2(acc2[3][q]));
                else
                    v = make_float4(lo2(acc2[0][q]), lo2(acc2[1][q]),
                                    lo2(acc2[2][q]), lo2(acc2[3][q]));
                *(float4*)(tsf + jl * 128 + ((ty ^ key) << 2)) = v;
            }
        }
        __syncthreads();
        #pragma unroll
        for (int s = 0; s < 4; s++) {
            int jl   = (warp << 2) | s;        // 0..63
            int jloc = (p << 6) + jl;          // actual j-local 0..127
            int key2 = jl >> 3;                // = (jloc>>3) & 7
            float4 val = *(const float4*)(tsf + jl * 128 + ((lane ^ key2) << 2));
            int gj = j0 + jloc;
            int gi = i0 + (lane << 2);
            if (gj < NN && gi < NN)
                __stcs((float4*)(out + (size_t)gj * NN + gi), val);
        }
    }
}

// ---------------- launch --------------------------------------------------
extern "C" void kernel_launch(void* const* d_in, const int* in_sizes, int n_in,
                              void* d_out, int out_size) {
    const float* x  = (const float*)d_in[0];
    const float* W1 = (const float*)d_in[1];
    const float* W2 = (const float*)d_in[2];
    const int*   ei = (const int*)  d_in[3];
    const float* ew = (const float*)d_in[4];

    float* out  = (float*)d_out;
    float* zout = out + (size_t)NN * NN;   // output layout: [adj (1e8) | z]

    k_build      <<<(EE + 255) / 256, 256>>>(ei, ew);
    k_gemm1      <<<(NN + 63) / 64, 256>>>(x, W1);
    k_spmm1_gemm2<<<(NN * 32 + 255) / 256, 256>>>(W2);
    k_spmm2      <<<(NN * 16) / 256, 256>>>(zout);
    k_dec        <<<NTRI, 512>>>(zout, out);
}

// round 8
// speedup vs baseline: 1.1031x; 1.1031x over previous
#include <cuda_runtime.h>
#include <cstdint>

#define NN   10000
#define EE   320000
#define FIN  512
#define NHID 32
#define LAT  16
#define PAD  128
#define TT   79      // ceil(10000/128) tiles per dim
#define NTRI 3160    // TT*(TT+1)/2

typedef unsigned long long u64;

// ---------------- device scratch (no allocations allowed) ----------------
// g_cnt invariant: zero at module load; k_spmm2 restores it to zero after
// its reads, so every kernel_launch call (and graph replay) sees zeros.
__device__ int   g_cnt[NN];
__device__ int2  g_adj[NN * PAD];     // (src, float-bits weight) interleaved
__device__ float g_h0 [NN * NHID];
__device__ float g_z0 [NN * LAT];

// ---------------- f32x2 packed helpers (sm_103a FFMA2 path) --------------
__device__ __forceinline__ u64 fma2(u64 a, u64 b, u64 c) {
    u64 d;
    asm("fma.rn.f32x2 %0, %1, %2, %3;" : "=l"(d) : "l"(a), "l"(b), "l"(c));
    return d;
}
__device__ __forceinline__ u64 pack2(float x) {
    u64 d; asm("mov.b64 %0, {%1, %1};" : "=l"(d) : "f"(x)); return d;
}
__device__ __forceinline__ float lo2(u64 v) {
    float f; asm("{ .reg .f32 h; mov.b64 {%0, h}, %1; }" : "=f"(f) : "l"(v)); return f;
}
__device__ __forceinline__ float hi2(u64 v) {
    float f; asm("{ .reg .f32 l; mov.b64 {l, %0}, %1; }" : "=f"(f) : "l"(v)); return f;
}
__device__ __forceinline__ float sigmoid_fast(float x) {
    float t;
    asm("tanh.approx.f32 %0, %1;" : "=f"(t) : "f"(0.5f * x));
    return fmaf(0.5f, t, 0.5f);
}
__device__ __forceinline__ u64 sig2(u64 x) {
    float lo = sigmoid_fast(lo2(x));
    float hi = sigmoid_fast(hi2(x));
    u64 r; asm("mov.b64 %0, {%1, %2};" : "=l"(r) : "f"(lo), "f"(hi));
    return r;
}

// ---------------- adjacency build (interleaved pairs, one STG.64) --------
__global__ void __launch_bounds__(256) k_build(const int* __restrict__ ei,
                                               const float* __restrict__ ew) {
    int e = blockIdx.x * blockDim.x + threadIdx.x;
    if (e >= EE) return;
    int   s = ei[e];
    int   d = ei[EE + e];
    float w = ew[e];
    int p = atomicAdd(&g_cnt[d], 1);
    if (p < PAD)
        g_adj[d * PAD + p] = make_int2(s, __float_as_int(w));
}

// ---------------- GEMM1: h0[N,32] = x[N,512] @ W1[512,32], FFMA2 ---------
__global__ void __launch_bounds__(256) k_gemm1(const float* __restrict__ x,
                                               const float* __restrict__ W1) {
    __shared__ float xs[64][28];
    __shared__ float w1s[16][32];

    int t    = threadIdx.x;
    int row0 = blockIdx.x * 64;
    int cg   = (t & 7) << 2;
    int rs   = (t >> 3) << 1;

    u64 a00 = 0ull, a01 = 0ull, a10 = 0ull, a11 = 0ull;

    for (int kk = 0; kk < FIN; kk += 16) {
        {
            int r  = t >> 2;
            int kq = (t & 3) << 2;
            int gr = row0 + r;
            float4 v = make_float4(0.f, 0.f, 0.f, 0.f);
            if (gr < NN) v = *(const float4*)(x + (size_t)gr * FIN + kk + kq);
            *(float4*)&xs[r][kq] = v;
        }
        if (t < 128) {
            int k = t >> 3, c = (t & 7) << 2;
            *(float4*)&w1s[k][c] = *(const float4*)(W1 + (size_t)(kk + k) * NHID + c);
        }
        __syncthreads();

        #pragma unroll
        for (int k = 0; k < 16; k++) {
            ulonglong2 bb = *(const ulonglong2*)&w1s[k][cg];
            u64 a0 = pack2(xs[rs][k]);
            u64 a1 = pack2(xs[rs + 1][k]);
            a00 = fma2(a0, bb.x, a00); a01 = fma2(a0, bb.y, a01);
            a10 = fma2(a1, bb.x, a10); a11 = fma2(a1, bb.y, a11);
        }
        __syncthreads();
    }

    int gr0 = row0 + rs;
    if (gr0 < NN)
        *(float4*)&g_h0[(size_t)gr0 * NHID + cg] =
            make_float4(lo2(a00), hi2(a00), lo2(a01), hi2(a01));
    if (gr0 + 1 < NN)
        *(float4*)&g_h0[(size_t)(gr0 + 1) * NHID + cg] =
            make_float4(lo2(a10), hi2(a10), lo2(a11), hi2(a11));
}

// ------- Fused SpMM1 + GEMM2: z0[d,:] = (sum_e w_e*h0[src_e,:]) @ W2 -----
// Warp per node; chunk-16 gathers (MLP 16, all L2-resident).
__global__ void __launch_bounds__(256) k_spmm1_gemm2(const float* __restrict__ W2) {
    __shared__ float w2s[NHID * LAT];
    {
        int t = threadIdx.x;
        for (int i = t; i < NHID * LAT; i += 256) w2s[i] = W2[i];
    }
    __syncthreads();

    int gid  = blockIdx.x * blockDim.x + threadIdx.x;
    int d    = gid >> 5;
    int lane = gid & 31;
    if (d >= NN) return;
    int cnt = g_cnt[d];
    if (cnt > PAD) cnt = PAD;
    const int2* ap = &g_adj[d * PAD];
    float acc = 0.f;
    int j = 0;
    for (; j + 16 <= cnt; j += 16) {
        int4 p0 = *(const int4*)(ap + j);
        int4 p1 = *(const int4*)(ap + j + 2);
        int4 p2 = *(const int4*)(ap + j + 4);
        int4 p3 = *(const int4*)(ap + j + 6);
        int4 p4 = *(const int4*)(ap + j + 8);
        int4 p5 = *(const int4*)(ap + j + 10);
        int4 p6 = *(const int4*)(ap + j + 12);
        int4 p7 = *(const int4*)(ap + j + 14);
        float v0  = g_h0[((size_t)p0.x << 5) + lane];
        float v1  = g_h0[((size_t)p0.z << 5) + lane];
        float v2  = g_h0[((size_t)p1.x << 5) + lane];
        float v3  = g_h0[((size_t)p1.z << 5) + lane];
        float v4  = g_h0[((size_t)p2.x << 5) + lane];
        float v5  = g_h0[((size_t)p2.z << 5) + lane];
        float v6  = g_h0[((size_t)p3.x << 5) + lane];
        float v7  = g_h0[((size_t)p3.z << 5) + lane];
        float v8  = g_h0[((size_t)p4.x << 5) + lane];
        float v9  = g_h0[((size_t)p4.z << 5) + lane];
        float v10 = g_h0[((size_t)p5.x << 5) + lane];
        float v11 = g_h0[((size_t)p5.z << 5) + lane];
        float v12 = g_h0[((size_t)p6.x << 5) + lane];
        float v13 = g_h0[((size_t)p6.z << 5) + lane];
        float v14 = g_h0[((size_t)p7.x << 5) + lane];
        float v15 = g_h0[((size_t)p7.z << 5) + lane];
        acc = fmaf(__int_as_float(p0.y), v0,  acc);
        acc = fmaf(__int_as_float(p0.w), v1,  acc);
        acc = fmaf(__int_as_float(p1.y), v2,  acc);
        acc = fmaf(__int_as_float(p1.w), v3,  acc);
        acc = fmaf(__int_as_float(p2.y), v4,  acc);
        acc = fmaf(__int_as_float(p2.w), v5,  acc);
        acc = fmaf(__int_as_float(p3.y), v6,  acc);
        acc = fmaf(__int_as_float(p3.w), v7,  acc);
        acc = fmaf(__int_as_float(p4.y), v8,  acc);
        acc = fmaf(__int_as_float(p4.w), v9,  acc);
        acc = fmaf(__int_as_float(p5.y), v10, acc);
        acc = fmaf(__int_as_float(p5.w), v11, acc);
        acc = fmaf(__int_as_float(p6.y), v12, acc);
        acc = fmaf(__int_as_float(p6.w), v13, acc);
        acc = fmaf(__int_as_float(p7.y), v14, acc);
        acc = fmaf(__int_as_float(p7.w), v15, acc);
    }
    for (; j < cnt; j++) {
        int2 e = ap[j];
        acc = fmaf(__int_as_float(e.y), g_h0[((size_t)e.x << 5) + lane], acc);
    }

    // h[d,:] distributed across lanes; z0[d,c] via shfl broadcast
    int c = lane & 15;
    float zc = 0.f;
    #pragma unroll
    for (int k = 0; k < NHID; k++) {
        float hk = __shfl_sync(0xffffffffu, acc, k);
        zc = fmaf(hk, w2s[k * LAT + c], zc);
    }
    if (lane < LAT)
        g_z0[((size_t)d << 4) + c] = zc;
}

// ------- SpMM2 (+ restore g_cnt=0 for the next call) ---------------------
// grid covers exactly NN*16 threads (625 blocks x 256) -> no divergent exit.
__global__ void __launch_bounds__(256) k_spmm2(float* __restrict__ zout) {
    int gid = blockIdx.x * blockDim.x + threadIdx.x;
    int d   = gid >> 4;
    int c   = gid & 15;
    int cnt = g_cnt[d];
    if (cnt > PAD) cnt = PAD;
    __syncwarp();                 // all reads of g_cnt in this warp done
    if (c == 0) g_cnt[d] = 0;     // restore invariant for next launch

    const int2* ap = &g_adj[d * PAD];
    float acc = 0.f;
    int j = 0;
    for (; j + 16 <= cnt; j += 16) {
        int4 p0 = *(const int4*)(ap + j);
        int4 p1 = *(const int4*)(ap + j + 2);
        int4 p2 = *(const int4*)(ap + j + 4);
        int4 p3 = *(const int4*)(ap + j + 6);
        int4 p4 = *(const int4*)(ap + j + 8);
        int4 p5 = *(const int4*)(ap + j + 10);
        int4 p6 = *(const int4*)(ap + j + 12);
        int4 p7 = *(const int4*)(ap + j + 14);
        float v0  = g_z0[((size_t)p0.x << 4) + c];
        float v1  = g_z0[((size_t)p0.z << 4) + c];
        float v2  = g_z0[((size_t)p1.x << 4) + c];
        float v3  = g_z0[((size_t)p1.z << 4) + c];
        float v4  = g_z0[((size_t)p2.x << 4) + c];
        float v5  = g_z0[((size_t)p2.z << 4) + c];
        float v6  = g_z0[((size_t)p3.x << 4) + c];
        float v7  = g_z0[((size_t)p3.z << 4) + c];
        float v8  = g_z0[((size_t)p4.x << 4) + c];
        float v9  = g_z0[((size_t)p4.z << 4) + c];
        float v10 = g_z0[((size_t)p5.x << 4) + c];
        float v11 = g_z0[((size_t)p5.z << 4) + c];
        float v12 = g_z0[((size_t)p6.x << 4) + c];
        float v13 = g_z0[((size_t)p6.z << 4) + c];
        float v14 = g_z0[((size_t)p7.x << 4) + c];
        float v15 = g_z0[((size_t)p7.z << 4) + c];
        acc = fmaf(__int_as_float(p0.y), v0,  acc);
        acc = fmaf(__int_as_float(p0.w), v1,  acc);
        acc = fmaf(__int_as_float(p1.y), v2,  acc);
        acc = fmaf(__int_as_float(p1.w), v3,  acc);
        acc = fmaf(__int_as_float(p2.y), v4,  acc);
        acc = fmaf(__int_as_float(p2.w), v5,  acc);
        acc = fmaf(__int_as_float(p3.y), v6,  acc);
        acc = fmaf(__int_as_float(p3.w), v7,  acc);
        acc = fmaf(__int_as_float(p4.y), v8,  acc);
        acc = fmaf(__int_as_float(p4.w), v9,  acc);
        acc = fmaf(__int_as_float(p5.y), v10, acc);
        acc = fmaf(__int_as_float(p5.w), v11, acc);
        acc = fmaf(__int_as_float(p6.y), v12, acc);
        acc = fmaf(__int_as_float(p6.w), v13, acc);
        acc = fmaf(__int_as_float(p7.y), v14, acc);
        acc = fmaf(__int_as_float(p7.w), v15, acc);
    }
    for (; j < cnt; j++) {
        int2 e = ap[j];
        acc = fmaf(__int_as_float(e.y), g_z0[((size_t)e.x << 4) + c], acc);
    }
    zout[((size_t)d << 4) + c] = acc;
}

// ---------------- Decoder: adj = sigmoid(z @ z^T), symmetric -------------
// R6 configuration (verbatim): 128x128 tile, 256 threads, 8x8/thread,
// FFMA2, conflict-free [k][part][group] float4 smem, XOR-swizzled mirror.
__global__ void __launch_bounds__(256, 2) k_dec(const float* __restrict__ z,
                                                float* __restrict__ out) {
    int b  = blockIdx.x;
    int bi = (int)((159.0f - sqrtf(25281.0f - 8.0f * (float)b)) * 0.5f);
    while (((bi + 1) * TT - ((bi + 1) * bi) / 2) <= b) bi++;
    while ((bi * TT - (bi * (bi - 1)) / 2) > b) bi--;
    int bj = bi + (b - (bi * TT - (bi * (bi - 1)) / 2));

    __shared__ union SmU {
        struct {
            float4 a[16][2][16];   // [k][part][group-of-8]
            float4 b[16][2][16];
        } in;                      // 16 KB
        float ts[64][128];         // swizzled transpose staging, 32 KB
    } sm;

    int t  = threadIdx.x;
    int i0 = bi * 128;
    int j0 = bj * 128;

    #pragma unroll
    for (int rep = 0; rep < 2; rep++) {
        int idx  = t + rep * 256;
        int r    = idx >> 2;
        int kq4  = idx & 3;
        int part = (r >> 2) & 1;
        int g    = r >> 3;
        int e    = r & 3;

        int gi = i0 + r;
        float4 v = make_float4(0.f, 0.f, 0.f, 0.f);
        if (gi < NN) v = *(const float4*)(z + (size_t)gi * LAT + kq4 * 4);
        ((float*)&sm.in.a[kq4 * 4 + 0][part][g])[e] = v.x;
        ((float*)&sm.in.a[kq4 * 4 + 1][part][g])[e] = v.y;
        ((float*)&sm.in.a[kq4 * 4 + 2][part][g])[e] = v.z;
        ((float*)&sm.in.a[kq4 * 4 + 3][part][g])[e] = v.w;

        int gj = j0 + r;
        float4 u = make_float4(0.f, 0.f, 0.f, 0.f);
        if (gj < NN) u = *(const float4*)(z + (size_t)gj * LAT + kq4 * 4);
        ((float*)&sm.in.b[kq4 * 4 + 0][part][g])[e] = u.x;
        ((float*)&sm.in.b[kq4 * 4 + 1][part][g])[e] = u.y;
        ((float*)&sm.in.b[kq4 * 4 + 2][part][g])[e] = u.z;
        ((float*)&sm.in.b[kq4 * 4 + 3][part][g])[e] = u.w;
    }
    __syncthreads();

    int tx = t & 15, ty = t >> 4;
    int ib = ty << 3, jb = tx << 3;

    u64 acc2[8][4];
    #pragma unroll
    for (int r = 0; r < 8; r++)
        #pragma unroll
        for (int q = 0; q < 4; q++) acc2[r][q] = 0ull;

    #pragma unroll
    for (int k = 0; k < 16; k++) {
        float4 Alo = sm.in.a[k][0][ty];
        float4 Ahi = sm.in.a[k][1][ty];
        ulonglong2 B0 = *(const ulonglong2*)&sm.in.b[k][0][tx];
        ulonglong2 B1 = *(const ulonglong2*)&sm.in.b[k][1][tx];
        u64 ar;
        ar = pack2(Alo.x);
        acc2[0][0] = fma2(ar, B0.x, acc2[0][0]); acc2[0][1] = fma2(ar, B0.y, acc2[0][1]);
        acc2[0][2] = fma2(ar, B1.x, acc2[0][2]); acc2[0][3] = fma2(ar, B1.y, acc2[0][3]);
        ar = pack2(Alo.y);
        acc2[1][0] = fma2(ar, B0.x, acc2[1][0]); acc2[1][1] = fma2(ar, B0.y, acc2[1][1]);
        acc2[1][2] = fma2(ar, B1.x, acc2[1][2]); acc2[1][3] = fma2(ar, B1.y, acc2[1][3]);
        ar = pack2(Alo.z);
        acc2[2][0] = fma2(ar, B0.x, acc2[2][0]); acc2[2][1] = fma2(ar, B0.y, acc2[2][1]);
        acc2[2][2] = fma2(ar, B1.x, acc2[2][2]); acc2[2][3] = fma2(ar, B1.y, acc2[2][3]);
        ar = pack2(Alo.w);
        acc2[3][0] = fma2(ar, B0.x, acc2[3][0]); acc2[3][1] = fma2(ar, B0.y, acc2[3][1]);
        acc2[3][2] = fma2(ar, B1.x, acc2[3][2]); acc2[3][3] = fma2(ar, B1.y, acc2[3][3]);
        ar = pack2(Ahi.x);
        acc2[4][0] = fma2(ar, B0.x, acc2[4][0]); acc2[4][1] = fma2(ar, B0.y, acc2[4][1]);
        acc2[4][2] = fma2(ar, B1.x, acc2[4][2]); acc2[4][3] = fma2(ar, B1.y, acc2[4][3]);
        ar = pack2(Ahi.y);
        acc2[5][0] = fma2(ar, B0.x, acc2[5][0]); acc2[5][1] = fma2(ar, B0.y, acc2[5][1]);
        acc2[5][2] = fma2(ar, B1.x, acc2[5][2]); acc2[5][3] = fma2(ar, B1.y, acc2[5][3]);
        ar = pack2(Ahi.z);
        acc2[6][0] = fma2(ar, B0.x, acc2[6][0]); acc2[6][1] = fma2(ar, B0.y, acc2[6][1]);
        acc2[6][2] = fma2(ar, B1.x, acc2[6][2]); acc2[6][3] = fma2(ar, B1.y, acc2[6][3]);
        ar = pack2(Ahi.w);
        acc2[7][0] = fma2(ar, B0.x, acc2[7][0]); acc2[7][1] = fma2(ar, B0.y, acc2[7][1]);
        acc2[7][2] = fma2(ar, B1.x, acc2[7][2]); acc2[7][3] = fma2(ar, B1.y, acc2[7][3]);
    }

    // ---- sigmoid + normal write interleaved per row ----
    int gjw = j0 + jb;
    #pragma unroll
    for (int r = 0; r < 8; r++) {
        acc2[r][0] = sig2(acc2[r][0]);
        acc2[r][1] = sig2(acc2[r][1]);
        acc2[r][2] = sig2(acc2[r][2]);
        acc2[r][3] = sig2(acc2[r][3]);
        int gi = i0 + ib + r;
        if (gi < NN && gjw < NN) {
            float4 o0 = make_float4(lo2(acc2[r][0]), hi2(acc2[r][0]),
                                    lo2(acc2[r][1]), hi2(acc2[r][1]));
            float4 o1 = make_float4(lo2(acc2[r][2]), hi2(acc2[r][2]),
                                    lo2(acc2[r][3]), hi2(acc2[r][3]));
            float* p = out + (size_t)gi * NN + gjw;
            __stcs((float4*)p, o0);
            __stcs((float4*)(p + 4), o1);
        }
    }

    if (bj == bi) return;

    // ---- mirror write: out[j][i], two 64-j-row swizzled transpose passes --
    int warp = t >> 5, lane = t & 31;
    int key  = tx & 7;
    float* tsf = (float*)sm.ts;
    #pragma unroll
    for (int p = 0; p < 2; p++) {
        __syncthreads();    // pass 0: done with in-tiles; pass 1: done with ts
        #pragma unroll
        for (int cc = 0; cc < 4; cc++) {
            int cpr  = (p << 2) + cc;
            int q    = cpr >> 1;
            int slot = (tx << 2) | cc;
            float4 v0, v1;
            if (cpr & 1) {
                v0 = make_float4(hi2(acc2[0][q]), hi2(acc2[1][q]),
                                 hi2(acc2[2][q]), hi2(acc2[3][q]));
                v1 = make_float4(hi2(acc2[4][q]), hi2(acc2[5][q]),
                                 hi2(acc2[6][q]), hi2(acc2[7][q]));
            } else {
                v0 = make_float4(lo2(acc2[0][q]), lo2(acc2[1][q]),
                                 lo2(acc2[2][q]), lo2(acc2[3][q]));
                v1 = make_float4(lo2(acc2[4][q]), lo2(acc2[5][q]),
                                 lo2(acc2[6][q]), lo2(acc2[7][q]));
            }
            int c4 = ib >> 2;
            *(float4*)(tsf + slot * 128 + (((c4)     ^ key) << 2)) = v0;
            *(float4*)(tsf + slot * 128 + (((c4 + 1) ^ key) << 2)) = v1;
        }
        __syncthreads();
        #pragma unroll
        for (int s8 = 0; s8 < 8; s8++) {
            int slot = (warp << 3) | s8;
            int txs  = slot >> 2;
            int jl   = (txs << 3) + (p << 2) + (slot & 3);
            int key2 = txs & 7;
            float4 val = *(const float4*)(tsf + slot * 128 + ((lane ^ key2) << 2));
            int gj = j0 + jl;
            int gi = i0 + (lane << 2);
            if (gj < NN && gi < NN)
                __stcs((float4*)(out + (size_t)gj * NN + gi), val);
        }
    }
}

// ---------------- launch --------------------------------------------------
extern "C" void kernel_launch(void* const* d_in, const int* in_sizes, int n_in,
                              void* d_out, int out_size) {
    const float* x  = (const float*)d_in[0];
    const float* W1 = (const float*)d_in[1];
    const float* W2 = (const float*)d_in[2];
    const int*   ei = (const int*)  d_in[3];
    const float* ew = (const float*)d_in[4];

    float* out  = (float*)d_out;
    float* zout = out + (size_t)NN * NN;   // output layout: [adj (1e8) | z]

    k_build      <<<(EE + 255) / 256, 256>>>(ei, ew);
    k_gemm1      <<<(NN + 63) / 64, 256>>>(x, W1);
    k_spmm1_gemm2<<<(NN * 32 + 255) / 256, 256>>>(W2);
    k_spmm2      <<<(NN * 16) / 256, 256>>>(zout);
    k_dec        <<<NTRI, 256>>>(zout, out);
}